// round 15
// baseline (speedup 1.0000x reference)
#include <cuda_runtime.h>
#include <cuda_bf16.h>
#include <cuda_fp16.h>
#include <cstdint>

#define L_TOK  8192
#define C_DIM  1024
#define INNER  1024
#define H_NUM  16
#define D_DIM  64
#define NSHIFT 16

#define BM 128
#define BN 256
#define NSTAGE 3
#define STAGE_F16 49152            // A 16K | B 32K
#define SMEM_F16  (NSTAGE * STAGE_F16)

#define ATOK 64                    // tokens per attention CTA
#define AWIN 128                   // smem window: 32 + 64 + 32

// ---------------- scratch ----------------------------------------------------
__device__ __align__(256) unsigned short g_xf16[L_TOK * 1024];     // fp16 x
__device__ __align__(256) unsigned short g_af16[L_TOK * 1024];     // fp16 attn out
__device__ __align__(256) unsigned short g_wqkv16[3072 * 1024];    // [n][k] fp16
__device__ __align__(256) unsigned short g_wo16 [1024 * 1024];     // [n][k] fp16
__device__ __align__(256) unsigned short g_q16[L_TOK * 1024];      // fp16 q
__device__ __align__(256) unsigned short g_k16[L_TOK * 1024];      // fp16 k
__device__ __align__(256) unsigned short g_v16[L_TOK * 1024];      // fp16 v
__device__ float g_bqkv[3072];
__device__ float g_ssq_q[L_TOK];
__device__ float g_ssq_k[L_TOK];

__constant__ int c_shift[NSHIFT] = {1,-1,2,-2,4,-4,8,-8,16,-16,32,-32, 1,-1,2,-2};

// ---------------- helpers ---------------------------------------------------
__device__ __forceinline__ uint32_t smem_u32(const void* p){
    uint32_t a;
    asm("{ .reg .u64 t; cvta.to.shared.u64 t, %1; cvt.u32.u64 %0, t; }" : "=r"(a) : "l"(p));
    return a;
}
__device__ __forceinline__ uint32_t pack_h2(float a, float b){
    __half2 h = __floats2half2_rn(a, b);
    return *(uint32_t*)&h;
}
__device__ __forceinline__ float2 unpack_h2(uint32_t u){
    return __half22float2(*(__half2*)&u);
}
__device__ __forceinline__ void cp16(uint32_t s, const void* g){
    asm volatile("cp.async.cg.shared.global [%0], [%1], 16;" :: "r"(s), "l"(g) : "memory");
}
__device__ __forceinline__ void ldsm_x4(uint32_t* r, uint32_t addr){
    asm volatile("ldmatrix.sync.aligned.m8n8.x4.shared.b16 {%0,%1,%2,%3}, [%4];"
        : "=r"(r[0]), "=r"(r[1]), "=r"(r[2]), "=r"(r[3]) : "r"(addr));
}
__device__ __forceinline__ void mma_f16(float* d, const uint32_t* a, uint32_t b0, uint32_t b1){
    asm volatile("mma.sync.aligned.m16n8k16.row.col.f32.f16.f16.f32 "
        "{%0,%1,%2,%3}, {%4,%5,%6,%7}, {%8,%9}, {%0,%1,%2,%3};"
        : "+f"(d[0]), "+f"(d[1]), "+f"(d[2]), "+f"(d[3])
        : "r"(a[0]), "r"(a[1]), "r"(a[2]), "r"(a[3]), "r"(b0), "r"(b1));
}

// ---------------- converters -------------------------------------------------
__global__ __launch_bounds__(256)
void conv_x(const float* __restrict__ x, uint32_t* __restrict__ f16)
{
    int gid = blockIdx.x * 256 + threadIdx.x;
    float4 f = ((const float4*)x)[gid];
    ((uint2*)f16)[gid] = make_uint2(pack_h2(f.x, f.y), pack_h2(f.z, f.w));
}

// All 4 weights in one launch. blockIdx.z: 0=Wq 1=Wk 2=Wv 3=Wo.
__global__ __launch_bounds__(256)
void conv_w_all(const float* __restrict__ Wq, const float* __restrict__ Wk,
                const float* __restrict__ Wv, const float* __restrict__ Wo,
                uint32_t* __restrict__ wqkv, uint32_t* __restrict__ wo)
{
    __shared__ float tile[32][33];
    const int t = threadIdx.x;
    const int tx = t & 31, ty = t >> 5;
    const int k0 = blockIdx.x * 32, n0 = blockIdx.y * 32;
    const int z = blockIdx.z;
    const float* W = (z == 0) ? Wq : (z == 1) ? Wk : (z == 2) ? Wv : Wo;
    uint32_t* dst  = (z == 3) ? wo : wqkv;
    const int n_off = (z == 3) ? 0 : z * 1024;
    #pragma unroll
    for (int r = 0; r < 4; r++) {
        int kl = ty + r * 8;
        tile[kl][tx] = W[(size_t)(k0 + kl) * 1024 + n0 + tx];
    }
    __syncthreads();
    #pragma unroll
    for (int w = 0; w < 2; w++) {
        int oid = t * 2 + w;
        int j = oid >> 4;
        int u = oid & 15;
        size_t idx = (size_t)(n_off + n0 + j) * 512 + (k0 >> 1) + u;
        dst[idx] = pack_h2(tile[2*u][j], tile[2*u+1][j]);
    }
}

__global__ void init_misc(const float* bq, const float* bk, const float* bv,
                          float* bqkv, float* ssq_q, float* ssq_k)
{
    int i = blockIdx.x * 256 + threadIdx.x;
    if (i < 1024)       bqkv[i] = bq[i];
    else if (i < 2048)  bqkv[i] = bk[i - 1024];
    else if (i < 3072)  bqkv[i] = bv[i - 2048];
    else {
        int j = i - 3072;
        if (j < L_TOK)          ssq_q[j] = 0.f;
        else if (j < 2*L_TOK)   ssq_k[j - L_TOK] = 0.f;
    }
}

// ssq -> rsqrt(mean + eps), in place
__global__ void rsqrt_prep(float* __restrict__ ssq_q, float* __restrict__ ssq_k)
{
    int i = blockIdx.x * 256 + threadIdx.x;
    if (i < L_TOK)          ssq_q[i] = rsqrtf(ssq_q[i] * (1.0f / INNER) + 1e-6f);
    else if (i < 2*L_TOK)   { int j = i - L_TOK; ssq_k[j] = rsqrtf(ssq_k[j] * (1.0f / INNER) + 1e-6f); }
}

// ---------------- 1-term fp16 GEMM, 128x256 tile -----------------------------
// 8 warps, 64x64 warp tile: ldsm:MMA = 32:128 (1.5x less smem per MMA).
// mode 0: Ntot=3072 -> q/k/v (fp16 outputs) + per-row sumsq for q,k.
// mode 1: single fp32 output.
__global__ __launch_bounds__(256, 1)
void gemm_f16(const unsigned short* __restrict__ A, const unsigned short* __restrict__ B,
              const float* __restrict__ bias,
              void* __restrict__ out0, void* __restrict__ out1, void* __restrict__ out2,
              float* __restrict__ ssq_q, float* __restrict__ ssq_k, int mode)
{
    extern __shared__ __align__(128) unsigned char smem[];
    const uint32_t sbase = smem_u32(smem);
    const int tid  = threadIdx.x;
    const int lane = tid & 31;
    const int wid  = tid >> 5;
    const int wm   = wid >> 2;          // 0..1  (64-row slice)
    const int wn   = wid & 3;           // 0..3  (64-col slice)
    const int mblk = blockIdx.y * BM;
    const int nblk = blockIdx.x * BN;

    auto load_stage = [&](int kc, int st){
        const uint32_t sb = sbase + st * STAGE_F16;
        // A: 128 rows x 128B = 16 KB
        #pragma unroll
        for (int j = 0; j < 4; j++) {
            int id  = tid + j * 256;
            int row = id >> 3;
            int c   = id & 7;
            uint32_t soff = row * 128 + ((c ^ (row & 7)) << 4);
            cp16(sb + soff, A + (size_t)(mblk + row) * 1024 + kc * 64 + c * 8);
        }
        // B: 256 rows x 128B = 32 KB
        #pragma unroll
        for (int j = 0; j < 8; j++) {
            int id  = tid + j * 256;
            int row = id >> 3;
            int c   = id & 7;
            uint32_t soff = 16384 + row * 128 + ((c ^ (row & 7)) << 4);
            cp16(sb + soff, B + (size_t)(nblk + row) * 1024 + kc * 64 + c * 8);
        }
        asm volatile("cp.async.commit_group;" ::: "memory");
    };

    float acc[4][8][4];
    #pragma unroll
    for (int i = 0; i < 4; i++)
        #pragma unroll
        for (int j = 0; j < 8; j++)
            #pragma unroll
            for (int e = 0; e < 4; e++) acc[i][j][e] = 0.f;

    load_stage(0, 0);
    load_stage(1, 1);

    for (int kc = 0; kc < 16; kc++) {
        if (kc < 15) asm volatile("cp.async.wait_group 1;" ::: "memory");
        else         asm volatile("cp.async.wait_group 0;" ::: "memory");
        __syncthreads();
        if (kc + 2 < 16) load_stage(kc + 2, (kc + 2) % NSTAGE);

        const uint32_t sb = sbase + (kc % NSTAGE) * STAGE_F16;
        const uint32_t sA = sb, sB = sb + 16384;

        #pragma unroll
        for (int s = 0; s < 4; s++) {
            const int c = 2 * s + (lane >> 4);
            uint32_t af[4][4];
            {
                int r = wm * 64 + (lane & 15);
                #pragma unroll
                for (int mt = 0; mt < 4; mt++) {
                    int rr = r + mt * 16;
                    ldsm_x4(af[mt], sA + rr * 128 + ((c ^ (rr & 7)) << 4));
                }
            }
            uint32_t bf[8][2];
            {
                int r = wn * 64 + (lane & 15);
                #pragma unroll
                for (int p = 0; p < 4; p++) {
                    int rr = r + p * 16;
                    uint32_t t4[4];
                    ldsm_x4(t4, sB + rr * 128 + ((c ^ (rr & 7)) << 4));
                    bf[p*2+0][0] = t4[0]; bf[p*2+0][1] = t4[2];
                    bf[p*2+1][0] = t4[1]; bf[p*2+1][1] = t4[3];
                }
            }
            #pragma unroll
            for (int mt = 0; mt < 4; mt++)
                #pragma unroll
                for (int nt = 0; nt < 8; nt++)
                    mma_f16(acc[mt][nt], af[mt], bf[nt][0], bf[nt][1]);
        }
    }

    // epilogue
    const int bi = nblk >> 10;          // mode 0: 0=q 1=k 2=v (BN=256 never crosses)
    float rsum[4][2];
    #pragma unroll
    for (int mt = 0; mt < 4; mt++) { rsum[mt][0] = 0.f; rsum[mt][1] = 0.f; }

    #pragma unroll
    for (int mt = 0; mt < 4; mt++) {
        #pragma unroll
        for (int nt = 0; nt < 8; nt++) {
            int m0  = mblk + wm * 64 + mt * 16 + (lane >> 2);
            int n_g = nblk + wn * 64 + nt * 8 + 2 * (lane & 3);
            float b0 = bias[n_g], b1 = bias[n_g + 1];
            float vx0 = acc[mt][nt][0] + b0, vy0 = acc[mt][nt][1] + b1;
            float vx1 = acc[mt][nt][2] + b0, vy1 = acc[mt][nt][3] + b1;
            if (mode == 0) {
                uint32_t* dst = (uint32_t*)((bi == 0) ? out0 : (bi == 1) ? out1 : out2);
                int nl = n_g & 1023;
                dst[(size_t)m0 * 512 + (nl >> 1)]       = pack_h2(vx0, vy0);
                dst[(size_t)(m0 + 8) * 512 + (nl >> 1)] = pack_h2(vx1, vy1);
                if (bi < 2) {
                    rsum[mt][0] += vx0 * vx0 + vy0 * vy0;
                    rsum[mt][1] += vx1 * vx1 + vy1 * vy1;
                }
            } else {
                float* dst = (float*)out0;
                *(float2*)&dst[(size_t)m0 * 1024 + n_g]       = make_float2(vx0, vy0);
                *(float2*)&dst[(size_t)(m0 + 8) * 1024 + n_g] = make_float2(vx1, vy1);
            }
        }
    }
    if (mode == 0 && bi < 2) {
        float* ssq = bi ? ssq_k : ssq_q;
        #pragma unroll
        for (int mt = 0; mt < 4; mt++) {
            #pragma unroll
            for (int h = 0; h < 2; h++) {
                float v = rsum[mt][h];
                v += __shfl_xor_sync(0xffffffffu, v, 1);
                v += __shfl_xor_sync(0xffffffffu, v, 2);
                if ((lane & 3) == 0) {
                    int row = mblk + wm * 64 + mt * 16 + (lane >> 2) + h * 8;
                    atomicAdd(&ssq[row], v);
                }
            }
        }
    }
}

// ---------------- small-world attention: smem spatial tiling ------------------
__global__ __launch_bounds__(128)
void attn_tile(const unsigned short* __restrict__ q16,
               const unsigned short* __restrict__ k16,
               const unsigned short* __restrict__ v16,
               const float* __restrict__ qn, const float* __restrict__ kn,
               const float* __restrict__ eb, const int* __restrict__ p_nf,
               const float* __restrict__ rsq_q, const float* __restrict__ rsq_k,
               uint32_t* __restrict__ af16)
{
    __shared__ uint32_t sk[AWIN][32];
    __shared__ uint32_t sv[AWIN][32];
    __shared__ float    srk[AWIN];
    __shared__ float    sbias[NSHIFT];

    const int tb   = blockIdx.x >> 4;
    const int head = blockIdx.x & 15;
    const int tok0 = tb * ATOK;
    const int tid  = threadIdx.x;

    int iv = *p_nf;
    int T;
    if (iv >= 1 && iv <= L_TOK && (L_TOK % iv) == 0) T = iv;
    else T = (int)__int_as_float(iv);
    const int S = L_TOK / T;

    const int t  = tok0 / S;
    const int s0 = tok0 - t * S;

    if (tid < NSHIFT) sbias[tid] = eb[head * NSHIFT + tid];
    for (int i = tid; i < AWIN * 8; i += 128) {
        int j = i >> 3, w = i & 7;
        int s_src = s0 - 32 + j;
        if (s_src < 0) s_src += S; else if (s_src >= S) s_src -= S;
        size_t rb = (size_t)(t * S + s_src) * 1024 + head * 64;
        ((uint4*)sk)[i] = *(const uint4*)&k16[rb + w * 8];
        ((uint4*)sv)[i] = *(const uint4*)&v16[rb + w * 8];
        if (w == 0) srk[j] = rsq_k[t * S + s_src];
    }
    __syncthreads();

    const int warp = tid >> 5, lane = tid & 31;
    const int half = lane >> 4, sub = lane & 15;
    const int dimg = head * D_DIM + sub * 4;

    float4 qw = *(const float4*)&qn[dimg];
    float4 kw = *(const float4*)&kn[dimg];
    float wgt0 = qw.x * kw.x, wgt1 = qw.y * kw.y, wgt2 = qw.z * kw.z, wgt3 = qw.w * kw.w;

    #pragma unroll 1
    for (int p = 0; p < 8; p++) {
        const int li  = warp * 16 + p * 2 + half;
        const int tok = tok0 + li;

        float pre = 0.125f * rsq_q[tok];
        uint2 qp = *(const uint2*)&q16[(size_t)tok * 1024 + dimg];
        float2 qa = unpack_h2(qp.x), qb = unpack_h2(qp.y);
        qa.x *= wgt0 * pre;  qa.y *= wgt1 * pre;
        qb.x *= wgt2 * pre;  qb.y *= wgt3 * pre;

        float sc[NSHIFT];
        uint2 vp[NSHIFT];
        #pragma unroll
        for (int n = 0; n < 12; n++) {
            int j = 32 + li + c_shift[n];
            uint2 kp = *(const uint2*)&sk[j][sub * 2];
            float2 k0 = unpack_h2(kp.x), k1 = unpack_h2(kp.y);
            float pw = qa.x * k0.x + qa.y * k0.y + qb.x * k1.x + qb.y * k1.y;
            pw += __shfl_xor_sync(0xffffffffu, pw, 8);
            pw += __shfl_xor_sync(0xffffffffu, pw, 4);
            pw += __shfl_xor_sync(0xffffffffu, pw, 2);
            pw += __shfl_xor_sync(0xffffffffu, pw, 1);
            sc[n] = pw * srk[j] + sbias[n];
            vp[n] = *(const uint2*)&sv[j][sub * 2];
        }
        #pragma unroll
        for (int n = 12; n < NSHIFT; n++) {
            int t2 = t + c_shift[n];
            while (t2 < 0)  t2 += T;
            while (t2 >= T) t2 -= T;
            int tok2 = t2 * S + s0 + li;
            size_t nb = (size_t)tok2 * 1024 + dimg;
            uint2 kp = *(const uint2*)&k16[nb];
            float2 k0 = unpack_h2(kp.x), k1 = unpack_h2(kp.y);
            float pw = qa.x * k0.x + qa.y * k0.y + qb.x * k1.x + qb.y * k1.y;
            pw += __shfl_xor_sync(0xffffffffu, pw, 8);
            pw += __shfl_xor_sync(0xffffffffu, pw, 4);
            pw += __shfl_xor_sync(0xffffffffu, pw, 2);
            pw += __shfl_xor_sync(0xffffffffu, pw, 1);
            sc[n] = pw * rsq_k[tok2] + sbias[n];
            vp[n] = *(const uint2*)&v16[nb];
        }

        float m = sc[0];
        #pragma unroll
        for (int n = 1; n < NSHIFT; n++) m = fmaxf(m, sc[n]);
        float sum = 0.f;
        #pragma unroll
        for (int n = 0; n < NSHIFT; n++) { sc[n] = __expf(sc[n] - m); sum += sc[n]; }
        float inv = 1.0f / sum;

        float a0 = 0.f, a1 = 0.f, a2 = 0.f, a3 = 0.f;
        #pragma unroll
        for (int n = 0; n < NSHIFT; n++) {
            float w = sc[n] * inv;
            float2 v0 = unpack_h2(vp[n].x), v1 = unpack_h2(vp[n].y);
            a0 += w * v0.x; a1 += w * v0.y;
            a2 += w * v1.x; a3 += w * v1.y;
        }

        uint2 o = make_uint2(pack_h2(a0, a1), pack_h2(a2, a3));
        *(uint2*)&af16[(size_t)tok * 512 + head * 32 + sub * 2] = o;
    }
}

// ---------------------------------------------------------------------------
extern "C" void kernel_launch(void* const* d_in, const int* in_sizes, int n_in,
                              void* d_out, int out_size)
{
    const float* x  = (const float*)d_in[0];
    const float* Wq = (const float*)d_in[1];
    const float* bq = (const float*)d_in[2];
    const float* Wk = (const float*)d_in[3];
    const float* bk = (const float*)d_in[4];
    const float* Wv = (const float*)d_in[5];
    const float* bv = (const float*)d_in[6];
    const float* qn = (const float*)d_in[7];
    const float* kn = (const float*)d_in[8];
    const float* eb = (const float*)d_in[9];
    const float* Wo = (const float*)d_in[10];
    const float* bo = (const float*)d_in[11];
    const int*   nf = (const int*)d_in[12];
    float* out = (float*)d_out;

    unsigned short *xf16,*af16,*wqkv,*wo16,*q16,*k16,*v16;
    float *bqkv,*ssq_q,*ssq_k;
    cudaGetSymbolAddress((void**)&xf16, g_xf16);
    cudaGetSymbolAddress((void**)&af16, g_af16);
    cudaGetSymbolAddress((void**)&wqkv, g_wqkv16);
    cudaGetSymbolAddress((void**)&wo16, g_wo16);
    cudaGetSymbolAddress((void**)&q16, g_q16);
    cudaGetSymbolAddress((void**)&k16, g_k16);
    cudaGetSymbolAddress((void**)&v16, g_v16);
    cudaGetSymbolAddress((void**)&bqkv, g_bqkv);
    cudaGetSymbolAddress((void**)&ssq_q, g_ssq_q);
    cudaGetSymbolAddress((void**)&ssq_k, g_ssq_k);

    cudaFuncSetAttribute(gemm_f16, cudaFuncAttributeMaxDynamicSharedMemorySize, SMEM_F16);

    init_misc<<<76, 256>>>(bq, bk, bv, bqkv, ssq_q, ssq_k);
    conv_x<<<8192, 256>>>(x, (uint32_t*)xf16);
    conv_w_all<<<dim3(32, 32, 4), 256>>>(Wq, Wk, Wv, Wo,
                                         (uint32_t*)wqkv, (uint32_t*)wo16);

    // fused QKV projection (N = 3072), fp16 outputs + per-row sumsq for q,k
    gemm_f16<<<dim3(12, 64), 256, SMEM_F16>>>(xf16, wqkv, bqkv,
                                              q16, k16, v16, ssq_q, ssq_k, 0);

    // fold mean+eps+rsqrt once per token
    rsqrt_prep<<<64, 256>>>(ssq_q, ssq_k);

    // attention: (L_TOK/64) token-blocks x 16 heads = 2048 CTAs, 128 threads
    attn_tile<<<(L_TOK / ATOK) * H_NUM, 128>>>(q16, k16, v16, qn, kn, eb, nf,
                                               ssq_q, ssq_k, (uint32_t*)af16);

    // output projection (fp32 out)
    gemm_f16<<<dim3(4, 64), 256, SMEM_F16>>>(af16, wo16, bo,
                                             out, out, out, nullptr, nullptr, 1);
}

// round 17
// speedup vs baseline: 1.1134x; 1.1134x over previous
#include <cuda_runtime.h>
#include <cuda_bf16.h>
#include <cuda_fp16.h>
#include <cstdint>

#define L_TOK  8192
#define C_DIM  1024
#define INNER  1024
#define H_NUM  16
#define D_DIM  64
#define NSHIFT 16

#define BM 128
#define BN 128
#define NSTAGE 3
#define STAGE_F16 32768            // A 16K | B 16K
#define SMEM_F16  (NSTAGE * STAGE_F16)

#define ATOK 64                    // tokens per attention CTA
#define AWIN 128                   // smem window: 32 + 64 + 32

// ---------------- scratch ----------------------------------------------------
__device__ __align__(256) unsigned short g_xf16[L_TOK * 1024];     // fp16 x
__device__ __align__(256) unsigned short g_af16[L_TOK * 1024];     // fp16 attn out
__device__ __align__(256) unsigned short g_wqkv16[3072 * 1024];    // [n][k] fp16
__device__ __align__(256) unsigned short g_wo16 [1024 * 1024];     // [n][k] fp16
__device__ __align__(256) unsigned short g_q16[L_TOK * 1024];      // fp16 q
__device__ __align__(256) unsigned short g_k16[L_TOK * 1024];      // fp16 k
__device__ __align__(256) unsigned short g_v16[L_TOK * 1024];      // fp16 v
__device__ float g_bqkv[3072];
__device__ float g_ssq_q[L_TOK];
__device__ float g_ssq_k[L_TOK];

__constant__ int c_shift[NSHIFT] = {1,-1,2,-2,4,-4,8,-8,16,-16,32,-32, 1,-1,2,-2};

// ---------------- helpers ---------------------------------------------------
__device__ __forceinline__ uint32_t smem_u32(const void* p){
    uint32_t a;
    asm("{ .reg .u64 t; cvta.to.shared.u64 t, %1; cvt.u32.u64 %0, t; }" : "=r"(a) : "l"(p));
    return a;
}
__device__ __forceinline__ uint32_t pack_h2(float a, float b){
    __half2 h = __floats2half2_rn(a, b);
    return *(uint32_t*)&h;
}
__device__ __forceinline__ float2 unpack_h2(uint32_t u){
    return __half22float2(*(__half2*)&u);
}
__device__ __forceinline__ void cp16(uint32_t s, const void* g){
    asm volatile("cp.async.cg.shared.global [%0], [%1], 16;" :: "r"(s), "l"(g) : "memory");
}
__device__ __forceinline__ void ldsm_x4(uint32_t* r, uint32_t addr){
    asm volatile("ldmatrix.sync.aligned.m8n8.x4.shared.b16 {%0,%1,%2,%3}, [%4];"
        : "=r"(r[0]), "=r"(r[1]), "=r"(r[2]), "=r"(r[3]) : "r"(addr));
}
__device__ __forceinline__ void mma_f16(float* d, const uint32_t* a, uint32_t b0, uint32_t b1){
    asm volatile("mma.sync.aligned.m16n8k16.row.col.f32.f16.f16.f32 "
        "{%0,%1,%2,%3}, {%4,%5,%6,%7}, {%8,%9}, {%0,%1,%2,%3};"
        : "+f"(d[0]), "+f"(d[1]), "+f"(d[2]), "+f"(d[3])
        : "r"(a[0]), "r"(a[1]), "r"(a[2]), "r"(a[3]), "r"(b0), "r"(b1));
}

// ---------------- converters -------------------------------------------------
// x fp32 -> fp16; trailing blocks (>= 8192) do bias concat + ssq zeroing.
__global__ __launch_bounds__(256)
void conv_x(const float* __restrict__ x, uint32_t* __restrict__ f16,
            const float* __restrict__ bq, const float* __restrict__ bk,
            const float* __restrict__ bv, float* __restrict__ bqkv,
            float* __restrict__ ssq_q, float* __restrict__ ssq_k)
{
    if (blockIdx.x < 8192) {
        int gid = blockIdx.x * 256 + threadIdx.x;
        float4 f = ((const float4*)x)[gid];
        ((uint2*)f16)[gid] = make_uint2(pack_h2(f.x, f.y), pack_h2(f.z, f.w));
    } else {
        int i = (blockIdx.x - 8192) * 256 + threadIdx.x;
        if (i < 1024)       bqkv[i] = bq[i];
        else if (i < 2048)  bqkv[i] = bk[i - 1024];
        else if (i < 3072)  bqkv[i] = bv[i - 2048];
        else {
            int j = i - 3072;
            if (j < L_TOK)          ssq_q[j] = 0.f;
            else if (j < 2*L_TOK)   ssq_k[j - L_TOK] = 0.f;
        }
    }
}

// All 4 weights in one launch. blockIdx.z: 0=Wq 1=Wk 2=Wv 3=Wo.
__global__ __launch_bounds__(256)
void conv_w_all(const float* __restrict__ Wq, const float* __restrict__ Wk,
                const float* __restrict__ Wv, const float* __restrict__ Wo,
                uint32_t* __restrict__ wqkv, uint32_t* __restrict__ wo)
{
    __shared__ float tile[32][33];
    const int t = threadIdx.x;
    const int tx = t & 31, ty = t >> 5;
    const int k0 = blockIdx.x * 32, n0 = blockIdx.y * 32;
    const int z = blockIdx.z;
    const float* W = (z == 0) ? Wq : (z == 1) ? Wk : (z == 2) ? Wv : Wo;
    uint32_t* dst  = (z == 3) ? wo : wqkv;
    const int n_off = (z == 3) ? 0 : z * 1024;
    #pragma unroll
    for (int r = 0; r < 4; r++) {
        int kl = ty + r * 8;
        tile[kl][tx] = W[(size_t)(k0 + kl) * 1024 + n0 + tx];
    }
    __syncthreads();
    #pragma unroll
    for (int w = 0; w < 2; w++) {
        int oid = t * 2 + w;
        int j = oid >> 4;
        int u = oid & 15;
        size_t idx = (size_t)(n_off + n0 + j) * 512 + (k0 >> 1) + u;
        dst[idx] = pack_h2(tile[2*u][j], tile[2*u+1][j]);
    }
}

// ---------------- 1-term fp16 GEMM (2 CTAs/SM) -------------------------------
// mode 0: Ntot=3072 -> q/k/v (fp16 outputs) + per-row sumsq for q,k.
// mode 1: single fp32 output.
__global__ __launch_bounds__(256, 2)
void gemm_f16(const unsigned short* __restrict__ A, const unsigned short* __restrict__ B,
              const float* __restrict__ bias,
              void* __restrict__ out0, void* __restrict__ out1, void* __restrict__ out2,
              float* __restrict__ ssq_q, float* __restrict__ ssq_k, int mode)
{
    extern __shared__ __align__(128) unsigned char smem[];
    const uint32_t sbase = smem_u32(smem);
    const int tid  = threadIdx.x;
    const int lane = tid & 31;
    const int wid  = tid >> 5;
    const int wm   = wid >> 2;
    const int wn   = wid & 3;
    const int mblk = blockIdx.y * BM;
    const int nblk = blockIdx.x * BN;

    auto load_stage = [&](int kc, int st){
        const uint32_t sb = sbase + st * STAGE_F16;
        #pragma unroll
        for (int mat = 0; mat < 2; mat++) {
            const unsigned short* gsrc = mat ? B : A;
            int rbase = mat ? nblk : mblk;
            #pragma unroll
            for (int j = 0; j < 4; j++) {
                int id  = tid + j * 256;
                int row = id >> 3;
                int c   = id & 7;
                uint32_t soff = mat * 16384 + row * 128 + ((c ^ (row & 7)) << 4);
                const void* g = gsrc + (size_t)(rbase + row) * 1024 + kc * 64 + c * 8;
                cp16(sb + soff, g);
            }
        }
        asm volatile("cp.async.commit_group;" ::: "memory");
    };

    float acc[4][4][4];
    #pragma unroll
    for (int i = 0; i < 4; i++)
        #pragma unroll
        for (int j = 0; j < 4; j++)
            #pragma unroll
            for (int e = 0; e < 4; e++) acc[i][j][e] = 0.f;

    load_stage(0, 0);
    load_stage(1, 1);

    for (int kc = 0; kc < 16; kc++) {
        if (kc < 15) asm volatile("cp.async.wait_group 1;" ::: "memory");
        else         asm volatile("cp.async.wait_group 0;" ::: "memory");
        __syncthreads();
        if (kc + 2 < 16) load_stage(kc + 2, (kc + 2) % NSTAGE);

        const uint32_t sb = sbase + (kc % NSTAGE) * STAGE_F16;
        const uint32_t sA = sb, sB = sb + 16384;

        #pragma unroll
        for (int s = 0; s < 4; s++) {
            uint32_t af[4][4];
            {
                int r = wm * 64 + (lane & 15);
                int c = 2 * s + (lane >> 4);
                #pragma unroll
                for (int mt = 0; mt < 4; mt++) {
                    int rr = r + mt * 16;
                    ldsm_x4(af[mt], sA + rr * 128 + ((c ^ (rr & 7)) << 4));
                }
            }
            uint32_t bf[4][2];
            {
                int r = wn * 32 + (lane & 15);
                int c = 2 * s + (lane >> 4);
                #pragma unroll
                for (int p = 0; p < 2; p++) {
                    int rr = r + p * 16;
                    uint32_t t4[4];
                    ldsm_x4(t4, sB + rr * 128 + ((c ^ (rr & 7)) << 4));
                    bf[p*2+0][0] = t4[0]; bf[p*2+0][1] = t4[2];
                    bf[p*2+1][0] = t4[1]; bf[p*2+1][1] = t4[3];
                }
            }
            #pragma unroll
            for (int mt = 0; mt < 4; mt++)
                #pragma unroll
                for (int nt = 0; nt < 4; nt++)
                    mma_f16(acc[mt][nt], af[mt], bf[nt][0], bf[nt][1]);
        }
    }

    // epilogue
    const int bi = nblk >> 10;          // mode 0: 0=q 1=k 2=v
    float rsum[4][2];
    #pragma unroll
    for (int mt = 0; mt < 4; mt++) { rsum[mt][0] = 0.f; rsum[mt][1] = 0.f; }

    #pragma unroll
    for (int mt = 0; mt < 4; mt++) {
        #pragma unroll
        for (int nt = 0; nt < 4; nt++) {
            int m0  = mblk + wm * 64 + mt * 16 + (lane >> 2);
            int n_g = nblk + wn * 32 + nt * 8 + 2 * (lane & 3);
            float b0 = bias[n_g], b1 = bias[n_g + 1];
            float vx0 = acc[mt][nt][0] + b0, vy0 = acc[mt][nt][1] + b1;
            float vx1 = acc[mt][nt][2] + b0, vy1 = acc[mt][nt][3] + b1;
            if (mode == 0) {
                uint32_t* dst = (uint32_t*)((bi == 0) ? out0 : (bi == 1) ? out1 : out2);
                int nl = n_g & 1023;
                dst[(size_t)m0 * 512 + (nl >> 1)]       = pack_h2(vx0, vy0);
                dst[(size_t)(m0 + 8) * 512 + (nl >> 1)] = pack_h2(vx1, vy1);
                if (bi < 2) {
                    rsum[mt][0] += vx0 * vx0 + vy0 * vy0;
                    rsum[mt][1] += vx1 * vx1 + vy1 * vy1;
                }
            } else {
                float* dst = (float*)out0;
                *(float2*)&dst[(size_t)m0 * 1024 + n_g]       = make_float2(vx0, vy0);
                *(float2*)&dst[(size_t)(m0 + 8) * 1024 + n_g] = make_float2(vx1, vy1);
            }
        }
    }
    if (mode == 0 && bi < 2) {
        float* ssq = bi ? ssq_k : ssq_q;
        #pragma unroll
        for (int mt = 0; mt < 4; mt++) {
            #pragma unroll
            for (int h = 0; h < 2; h++) {
                float v = rsum[mt][h];
                v += __shfl_xor_sync(0xffffffffu, v, 1);
                v += __shfl_xor_sync(0xffffffffu, v, 2);
                if ((lane & 3) == 0) {
                    int row = mblk + wm * 64 + mt * 16 + (lane >> 2) + h * 8;
                    atomicAdd(&ssq[row], v);
                }
            }
        }
    }
}

// ---------------- small-world attention: smem spatial tiling ------------------
// rsqrt factors computed ONCE per CTA at staging time (ssq arrays hold raw sums).
__global__ __launch_bounds__(128)
void attn_tile(const unsigned short* __restrict__ q16,
               const unsigned short* __restrict__ k16,
               const unsigned short* __restrict__ v16,
               const float* __restrict__ qn, const float* __restrict__ kn,
               const float* __restrict__ eb, const int* __restrict__ p_nf,
               const float* __restrict__ ssq_q, const float* __restrict__ ssq_k,
               uint32_t* __restrict__ af16)
{
    __shared__ uint32_t sk[AWIN][32];
    __shared__ uint32_t sv[AWIN][32];
    __shared__ float    srk[AWIN];        // rsqrt for spatial window rows
    __shared__ float    srkt[4][ATOK];    // rsqrt for temporal neighbor rows
    __shared__ float    sqr[ATOK];        // rsqrt for q rows
    __shared__ float    sbias[NSHIFT];

    const int tb   = blockIdx.x >> 4;
    const int head = blockIdx.x & 15;
    const int tok0 = tb * ATOK;
    const int tid  = threadIdx.x;

    int iv = *p_nf;
    int T;
    if (iv >= 1 && iv <= L_TOK && (L_TOK % iv) == 0) T = iv;
    else T = (int)__int_as_float(iv);
    const int S = L_TOK / T;

    const int t  = tok0 / S;
    const int s0 = tok0 - t * S;

    if (tid < NSHIFT) sbias[tid] = eb[head * NSHIFT + tid];
    if (tid < ATOK) sqr[tid] = rsqrtf(ssq_q[tok0 + tid] * (1.0f / INNER) + 1e-6f);
    for (int i = tid; i < 4 * ATOK; i += 128) {
        int si = i >> 6, li = i & 63;
        int t2 = t + c_shift[12 + si];
        if (t2 < 0) t2 += T; else if (t2 >= T) t2 -= T;
        srkt[si][li] = rsqrtf(ssq_k[t2 * S + s0 + li] * (1.0f / INNER) + 1e-6f);
    }
    for (int i = tid; i < AWIN * 8; i += 128) {
        int j = i >> 3, w = i & 7;
        int s_src = s0 - 32 + j;
        if (s_src < 0) s_src += S; else if (s_src >= S) s_src -= S;
        size_t rb = (size_t)(t * S + s_src) * 1024 + head * 64;
        ((uint4*)sk)[i] = *(const uint4*)&k16[rb + w * 8];
        ((uint4*)sv)[i] = *(const uint4*)&v16[rb + w * 8];
        if (w == 0) srk[j] = rsqrtf(ssq_k[t * S + s_src] * (1.0f / INNER) + 1e-6f);
    }
    __syncthreads();

    const int warp = tid >> 5, lane = tid & 31;
    const int half = lane >> 4, sub = lane & 15;
    const int dimg = head * D_DIM + sub * 4;

    float4 qw = *(const float4*)&qn[dimg];
    float4 kw = *(const float4*)&kn[dimg];
    float wgt0 = qw.x * kw.x, wgt1 = qw.y * kw.y, wgt2 = qw.z * kw.z, wgt3 = qw.w * kw.w;

    #pragma unroll 1
    for (int p = 0; p < 8; p++) {
        const int li  = warp * 16 + p * 2 + half;
        const int tok = tok0 + li;

        float pre = 0.125f * sqr[li];
        uint2 qp = *(const uint2*)&q16[(size_t)tok * 1024 + dimg];
        float2 qa = unpack_h2(qp.x), qb = unpack_h2(qp.y);
        qa.x *= wgt0 * pre;  qa.y *= wgt1 * pre;
        qb.x *= wgt2 * pre;  qb.y *= wgt3 * pre;

        float sc[NSHIFT];
        uint2 vp[NSHIFT];
        #pragma unroll
        for (int n = 0; n < 12; n++) {
            int j = 32 + li + c_shift[n];
            uint2 kp = *(const uint2*)&sk[j][sub * 2];
            float2 k0 = unpack_h2(kp.x), k1 = unpack_h2(kp.y);
            float pw = qa.x * k0.x + qa.y * k0.y + qb.x * k1.x + qb.y * k1.y;
            pw += __shfl_xor_sync(0xffffffffu, pw, 8);
            pw += __shfl_xor_sync(0xffffffffu, pw, 4);
            pw += __shfl_xor_sync(0xffffffffu, pw, 2);
            pw += __shfl_xor_sync(0xffffffffu, pw, 1);
            sc[n] = pw * srk[j] + sbias[n];
            vp[n] = *(const uint2*)&sv[j][sub * 2];
        }
        #pragma unroll
        for (int n = 12; n < NSHIFT; n++) {
            int t2 = t + c_shift[n];
            if (t2 < 0) t2 += T; else if (t2 >= T) t2 -= T;
            int tok2 = t2 * S + s0 + li;
            size_t nb = (size_t)tok2 * 1024 + dimg;
            uint2 kp = *(const uint2*)&k16[nb];
            float2 k0 = unpack_h2(kp.x), k1 = unpack_h2(kp.y);
            float pw = qa.x * k0.x + qa.y * k0.y + qb.x * k1.x + qb.y * k1.y;
            pw += __shfl_xor_sync(0xffffffffu, pw, 8);
            pw += __shfl_xor_sync(0xffffffffu, pw, 4);
            pw += __shfl_xor_sync(0xffffffffu, pw, 2);
            pw += __shfl_xor_sync(0xffffffffu, pw, 1);
            sc[n] = pw * srkt[n - 12][li] + sbias[n];
            vp[n] = *(const uint2*)&v16[nb];
        }

        float m = sc[0];
        #pragma unroll
        for (int n = 1; n < NSHIFT; n++) m = fmaxf(m, sc[n]);
        float sum = 0.f;
        #pragma unroll
        for (int n = 0; n < NSHIFT; n++) { sc[n] = __expf(sc[n] - m); sum += sc[n]; }
        float inv = 1.0f / sum;

        float a0 = 0.f, a1 = 0.f, a2 = 0.f, a3 = 0.f;
        #pragma unroll
        for (int n = 0; n < NSHIFT; n++) {
            float w = sc[n] * inv;
            float2 v0 = unpack_h2(vp[n].x), v1 = unpack_h2(vp[n].y);
            a0 += w * v0.x; a1 += w * v0.y;
            a2 += w * v1.x; a3 += w * v1.y;
        }

        uint2 o = make_uint2(pack_h2(a0, a1), pack_h2(a2, a3));
        *(uint2*)&af16[(size_t)tok * 512 + head * 32 + sub * 2] = o;
    }
}

// ---------------------------------------------------------------------------
extern "C" void kernel_launch(void* const* d_in, const int* in_sizes, int n_in,
                              void* d_out, int out_size)
{
    const float* x  = (const float*)d_in[0];
    const float* Wq = (const float*)d_in[1];
    const float* bq = (const float*)d_in[2];
    const float* Wk = (const float*)d_in[3];
    const float* bk = (const float*)d_in[4];
    const float* Wv = (const float*)d_in[5];
    const float* bv = (const float*)d_in[6];
    const float* qn = (const float*)d_in[7];
    const float* kn = (const float*)d_in[8];
    const float* eb = (const float*)d_in[9];
    const float* Wo = (const float*)d_in[10];
    const float* bo = (const float*)d_in[11];
    const int*   nf = (const int*)d_in[12];
    float* out = (float*)d_out;

    unsigned short *xf16,*af16,*wqkv,*wo16,*q16,*k16,*v16;
    float *bqkv,*ssq_q,*ssq_k;
    cudaGetSymbolAddress((void**)&xf16, g_xf16);
    cudaGetSymbolAddress((void**)&af16, g_af16);
    cudaGetSymbolAddress((void**)&wqkv, g_wqkv16);
    cudaGetSymbolAddress((void**)&wo16, g_wo16);
    cudaGetSymbolAddress((void**)&q16, g_q16);
    cudaGetSymbolAddress((void**)&k16, g_k16);
    cudaGetSymbolAddress((void**)&v16, g_v16);
    cudaGetSymbolAddress((void**)&bqkv, g_bqkv);
    cudaGetSymbolAddress((void**)&ssq_q, g_ssq_q);
    cudaGetSymbolAddress((void**)&ssq_k, g_ssq_k);

    cudaFuncSetAttribute(gemm_f16, cudaFuncAttributeMaxDynamicSharedMemorySize, SMEM_F16);

    // x convert + bias concat + ssq zero in one launch (8192 + 76 blocks)
    conv_x<<<8192 + 76, 256>>>(x, (uint32_t*)xf16, bq, bk, bv, bqkv, ssq_q, ssq_k);
    conv_w_all<<<dim3(32, 32, 4), 256>>>(Wq, Wk, Wv, Wo,
                                         (uint32_t*)wqkv, (uint32_t*)wo16);

    // fused QKV projection (N = 3072), fp16 outputs + per-row sumsq for q,k
    gemm_f16<<<dim3(24, 64), 256, SMEM_F16>>>(xf16, wqkv, bqkv,
                                              q16, k16, v16, ssq_q, ssq_k, 0);

    // attention: (L_TOK/64) token-blocks x 16 heads = 2048 CTAs, 128 threads
    attn_tile<<<(L_TOK / ATOK) * H_NUM, 128>>>(q16, k16, v16, qn, kn, eb, nf,
                                               ssq_q, ssq_k, (uint32_t*)af16);

    // output projection (fp32 out): BN=128 -> grid (8, 64)
    gemm_f16<<<dim3(8, 64), 256, SMEM_F16>>>(af16, wo16, bo,
                                             out, out, out, nullptr, nullptr, 1);
}